// round 7
// baseline (speedup 1.0000x reference)
#include <cuda_runtime.h>
#include <cuda_bf16.h>
#include <math.h>

#define B_ 16
#define T_ 2048
#define C_ 1024
#define H_ 64
#define M_ (B_ * T_)   // 32768

typedef unsigned int u32;
typedef unsigned short u16;

// ---------------- static device scratch (no allocations) ----------------
// Q, K row-major [m][32 u32-pairs], fragment-permuted within each 32-pair row.
__device__ u32 g_qh[(size_t)M_ * 32], g_ql[(size_t)M_ * 32];
__device__ u32 g_kh[(size_t)M_ * 32], g_kl[(size_t)M_ * 32];
// V transposed per batch: [b][h=64][t-pairs 1024], fragment-permuted per 32-pair group.
__device__ u32 g_vth[(size_t)B_ * 64 * 1024], g_vtl[(size_t)B_ * 64 * 1024];
// W transposed: [w=3][n=64][k-pairs 512], permuted per 16-pair tile.
__device__ u32 g_wth[3 * 64 * 512], g_wtl[3 * 64 * 512];

// split-K partials: q-tiles of 64 rows, chunks of <=256 keys.
#define NQT 32
#define NCH_TOT 144
#define NSLOT (B_ * NCH_TOT)        // 2304
__device__ float part_o[(size_t)NSLOT * 64 * H_];
__device__ float part_m[NSLOT * 64];
__device__ float part_l[NSLOT * 64];

__constant__ int c_base[NQT + 1] = {
    0,1,2,3, 4,6,8,10, 12,15,18,21, 24,28,32,36,
    40,45,50,55, 60,66,72,78, 84,91,98,105, 112,120,128,136, 144 };

#define LOG2E 1.4426950408889634f

// ---------------- helpers ----------------
// fragment permutation: logical pair c -> physical slot, pairs (c, c+4) adjacent
__device__ __host__ __forceinline__ int phys32(int c) {   // c in [0,32)
    return (c & 24) | ((c & 3) << 1) | ((c >> 2) & 1);
}
__device__ __forceinline__ int phys16(int c) {            // c in [0,16)
    return (c & 8) | ((c & 3) << 1) | ((c >> 2) & 1);
}
// V column mapping: logical t -> permuted u16 index within a 64-wide group
__device__ __forceinline__ int vt_off(int t) {
    int lp = (t >> 1) & 31;
    return ((t >> 6) << 6) + (phys32(lp) << 1) + (t & 1);
}

__device__ __forceinline__ void split1(float x, u16& h, u16& l) {
    __nv_bfloat16 bh = __float2bfloat16_rn(x);
    float r = x - __bfloat162float(bh);
    __nv_bfloat16 bl = __float2bfloat16_rn(r);
    h = __bfloat16_as_ushort(bh);
    l = __bfloat16_as_ushort(bl);
}
__device__ __forceinline__ void split2(float a, float b, u32& hi, u32& lo) {
    u16 ha, la, hb, lb;
    split1(a, ha, la);
    split1(b, hb, lb);
    hi = (u32)ha | ((u32)hb << 16);
    lo = (u32)la | ((u32)lb << 16);
}
__device__ __forceinline__ float fexp2(float x) {
    float y; asm("ex2.approx.f32 %0,%1;" : "=f"(y) : "f"(x)); return y;
}

// m16n8k16 bf16 MMA, fp32 accumulate (D += A*B)
__device__ __forceinline__ void mma_bf16(float* c,
    u32 a0, u32 a1, u32 a2, u32 a3, u32 b0, u32 b1) {
    asm volatile(
        "mma.sync.aligned.m16n8k16.row.col.f32.bf16.bf16.f32 "
        "{%0,%1,%2,%3},{%4,%5,%6,%7},{%8,%9},{%0,%1,%2,%3};"
        : "+f"(c[0]), "+f"(c[1]), "+f"(c[2]), "+f"(c[3])
        : "r"(a0), "r"(a1), "r"(a2), "r"(a3), "r"(b0), "r"(b1));
}

// ---------------------------------------------------------------------------
// W pre-convert: W[c][h] f32 -> [w][n][k-pair] bf16 hi/lo, phys16-permuted.
// ---------------------------------------------------------------------------
__global__ void wconv_kernel(const float* __restrict__ wq,
                             const float* __restrict__ wk,
                             const float* __restrict__ wv) {
    int idx = blockIdx.x * 256 + threadIdx.x;
    if (idx >= 3 * 64 * 512) return;
    int w   = idx / (64 * 512);
    int rem = idx % (64 * 512);
    int n   = rem / 512;
    int kp  = rem % 512;                         // logical pair index
    const float* W = (w == 0) ? wq : (w == 1 ? wk : wv);
    float a = W[(size_t)(2 * kp) * 64 + n];
    float b = W[(size_t)(2 * kp + 1) * 64 + n];
    u32 hi, lo;
    split2(a, b, hi, lo);
    int dst = w * 32768 + n * 512 + (kp & ~15) + phys16(kp & 15);
    g_wth[dst] = hi;
    g_wtl[dst] = lo;
}

// ---------------------------------------------------------------------------
// Fused projection: one CTA computes Q, K, V for a 64-row X tile.
// grid = 512, block = 128 (4 warps x m16). BK = 32. X converted ONCE.
// Q pre-scaled by 0.125*log2(e) (exp2-domain softmax).
// ---------------------------------------------------------------------------
__global__ __launch_bounds__(128) void proj_kernel(const float* __restrict__ x)
{
    __shared__ __align__(16) u32 xh[64 * 20], xl[64 * 20];  // 16 pairs + pad4
    __shared__ __align__(16) u32 wsm[6 * 64 * 24];          // [2sel+plane][n][pair]

    const int tid  = threadIdx.x;
    const int w    = tid >> 5;
    const int lane = tid & 31;
    const int g    = lane >> 2;
    const int tig  = lane & 3;
    const int m0   = blockIdx.x * 64;

    float acc[3][8][4];
#pragma unroll
    for (int s = 0; s < 3; s++)
#pragma unroll
        for (int nt = 0; nt < 8; nt++)
#pragma unroll
            for (int i = 0; i < 4; i++) acc[s][nt][i] = 0.0f;

    for (int k0 = 0; k0 < C_; k0 += 32) {
        const int kp0 = k0 >> 1;
        __syncthreads();
        // stage X 64x32 f32 -> hi/lo pairs, phys16-permuted
#pragma unroll
        for (int q = 0; q < 4; q++) {
            int i  = tid + 128 * q;
            int r  = i >> 3;
            int kq = i & 7;
            float4 v = *(const float4*)(x + (size_t)(m0 + r) * C_ + k0 + kq * 4);
            u32 h0, l0, h1, l1;
            split2(v.x, v.y, h0, l0);
            split2(v.z, v.w, h1, l1);
            int p0 = phys16(2 * kq), p1 = phys16(2 * kq + 1);
            xh[r * 20 + p0] = h0;  xh[r * 20 + p1] = h1;
            xl[r * 20 + p0] = l0;  xl[r * 20 + p1] = l1;
        }
        // stage 6 W planes (pre-permuted): 1536 float4
#pragma unroll
        for (int q = 0; q < 12; q++) {
            int i   = tid + 128 * q;
            int ps  = i >> 8;            // 0..5 = 2*sel+plane
            int rem = i & 255;
            int n   = rem >> 2;
            int c4  = rem & 3;
            const u32* src = ((ps & 1) ? g_wtl : g_wth)
                             + (ps >> 1) * 32768 + n * 512 + kp0 + 4 * c4;
            *(float4*)&wsm[ps * 1536 + n * 24 + 4 * c4] = *(const float4*)src;
        }
        __syncthreads();

        const int rg  = (16 * w + g) * 20;
        const int rg8 = rg + 160;
#pragma unroll
        for (int ks = 0; ks < 2; ks++) {
            const int c0 = 8 * ks + 2 * tig;
            uint2 AH0 = *(const uint2*)&xh[rg  + c0];   // (a0, a2)
            uint2 AH1 = *(const uint2*)&xh[rg8 + c0];   // (a1, a3)
            uint2 AL0 = *(const uint2*)&xl[rg  + c0];
            uint2 AL1 = *(const uint2*)&xl[rg8 + c0];
#pragma unroll
            for (int s = 0; s < 3; s++) {
#pragma unroll
                for (int nt = 0; nt < 8; nt++) {
                    int br = (8 * nt + g) * 24 + c0;
                    uint2 BH = *(const uint2*)&wsm[(2 * s)     * 1536 + br];
                    uint2 BL = *(const uint2*)&wsm[(2 * s + 1) * 1536 + br];
                    mma_bf16(acc[s][nt], AH0.x, AH1.x, AH0.y, AH1.y, BH.x, BH.y);
                    mma_bf16(acc[s][nt], AH0.x, AH1.x, AH0.y, AH1.y, BL.x, BL.y);
                    mma_bf16(acc[s][nt], AL0.x, AL1.x, AL0.y, AL1.y, BH.x, BH.y);
                }
            }
        }
    }

    // ---- epilogues ----
    const int mg = m0 + 16 * w + g;       // rows mg (c0,c1) and mg+8 (c2,c3)
    // Q (scaled, exp2 domain) and K: permuted row layout
#pragma unroll
    for (int s = 0; s < 2; s++) {
        u32* Hp = s ? g_kh : g_qh;
        u32* Lp = s ? g_kl : g_ql;
        const float sc = s ? 1.0f : (0.125f * LOG2E);
#pragma unroll
        for (int nt = 0; nt < 8; nt++) {
            int pos = phys32(4 * nt + tig);
            u32 hi, lo;
            split2(sc * acc[s][nt][0], sc * acc[s][nt][1], hi, lo);
            Hp[(size_t)mg * 32 + pos] = hi;
            Lp[(size_t)mg * 32 + pos] = lo;
            split2(sc * acc[s][nt][2], sc * acc[s][nt][3], hi, lo);
            Hp[(size_t)(mg + 8) * 32 + pos] = hi;
            Lp[(size_t)(mg + 8) * 32 + pos] = lo;
        }
    }
    // V transposed, permuted t-columns
    {
        u16* VH = (u16*)g_vth;
        u16* VL = (u16*)g_vtl;
        const int b  = mg >> 11;
        const int tt = mg & 2047;
        const int o0 = vt_off(tt);
        const int o8 = vt_off(tt + 8);
#pragma unroll
        for (int nt = 0; nt < 8; nt++) {
            int h0 = 8 * nt + 2 * tig;
            size_t r0 = ((size_t)(b * 64 + h0)) * 2048;
            size_t r1 = ((size_t)(b * 64 + h0 + 1)) * 2048;
            u16 hh, ll;
            split1(acc[2][nt][0], hh, ll); VH[r0 + o0] = hh; VL[r0 + o0] = ll;
            split1(acc[2][nt][1], hh, ll); VH[r1 + o0] = hh; VL[r1 + o0] = ll;
            split1(acc[2][nt][2], hh, ll); VH[r0 + o8] = hh; VL[r0 + o8] = ll;
            split1(acc[2][nt][3], hh, ll); VH[r1 + o8] = hh; VL[r1 + o8] = ll;
        }
    }
}

// ---------------------------------------------------------------------------
// Split-K flash-attention chunk: CTA = 64 q-rows x <=256 keys.
// grid = (144, 16), block = 128. exp2-domain softmax; P split hi+lo (accurate).
// ---------------------------------------------------------------------------
__global__ __launch_bounds__(128) void attn_chunk_kernel()
{
    __shared__ __align__(16) u32 Kh[64 * 40], Kl[64 * 40];   // stride 40: conflict-free LDS.64
    __shared__ __align__(16) u32 Vh[64 * 40], Vl[64 * 40];

    const int s = blockIdx.x;
    const int b = blockIdx.y;
    int qt = 0;
    while (c_base[qt + 1] <= s) qt++;
    const int ci = s - c_base[qt];
    const int q0 = qt * 64;

    const int tid  = threadIdx.x;
    const int w    = tid >> 5;
    const int lane = tid & 31;
    const int g    = lane >> 2;
    const int tig  = lane & 3;

    const int kbeg = ci * 256;
    const int kend = min(kbeg + 256, q0 + 64);

    // resident Q fragments via uint2 (gmem pre-permuted)
    uint2 qh0[4], qh1[4], ql0[4], ql1[4];
    {
        const size_t qr  = ((size_t)b * T_ + q0 + 16 * w + g) * 32;
        const size_t qr8 = qr + 8 * 32;
#pragma unroll
        for (int ks = 0; ks < 4; ks++) {
            int c0 = 8 * ks + 2 * tig;
            qh0[ks] = *(const uint2*)&g_qh[qr  + c0];
            qh1[ks] = *(const uint2*)&g_qh[qr8 + c0];
            ql0[ks] = *(const uint2*)&g_ql[qr  + c0];
            ql1[ks] = *(const uint2*)&g_ql[qr8 + c0];
        }
    }

    float o[8][4];
#pragma unroll
    for (int ht = 0; ht < 8; ht++)
#pragma unroll
        for (int i = 0; i < 4; i++) o[ht][i] = 0.0f;
    float m0r = -INFINITY, m1r = -INFINITY, l0 = 0.0f, l1 = 0.0f;

    for (int kb = kbeg; kb < kend; kb += 64) {
        __syncthreads();
        {
            const float4* KH = (const float4*)(g_kh + ((size_t)b * T_ + kb) * 32);
            const float4* KL = (const float4*)(g_kl + ((size_t)b * T_ + kb) * 32);
            const float4* VH = (const float4*)(g_vth + (size_t)b * 64 * 1024 + (kb >> 1));
            const float4* VL = (const float4*)(g_vtl + (size_t)b * 64 * 1024 + (kb >> 1));
#pragma unroll
            for (int q = 0; q < 4; q++) {
                int i  = tid + 128 * q;
                int r  = i >> 3;
                int c4 = i & 7;
                *(float4*)&Kh[r * 40 + 4 * c4] = KH[r * 8 + c4];
                *(float4*)&Kl[r * 40 + 4 * c4] = KL[r * 8 + c4];
                *(float4*)&Vh[r * 40 + 4 * c4] = VH[r * 256 + c4];
                *(float4*)&Vl[r * 40 + 4 * c4] = VL[r * 256 + c4];
            }
        }
        __syncthreads();

        // ---- S = Q K^T (exp2-domain scale pre-folded into Q) ----
        float sA[8][4];
#pragma unroll
        for (int nt = 0; nt < 8; nt++)
#pragma unroll
            for (int i = 0; i < 4; i++) sA[nt][i] = 0.0f;
#pragma unroll
        for (int ks = 0; ks < 4; ks++) {
            const int c0 = 8 * ks + 2 * tig;
#pragma unroll
            for (int nt = 0; nt < 8; nt++) {
                int br = (8 * nt + g) * 40 + c0;
                uint2 BH = *(const uint2*)&Kh[br];
                uint2 BL = *(const uint2*)&Kl[br];
                mma_bf16(sA[nt], qh0[ks].x, qh1[ks].x, qh0[ks].y, qh1[ks].y, BH.x, BH.y);
                mma_bf16(sA[nt], qh0[ks].x, qh1[ks].x, qh0[ks].y, qh1[ks].y, BL.x, BL.y);
                mma_bf16(sA[nt], ql0[ks].x, ql1[ks].x, ql0[ks].y, ql1[ks].y, BH.x, BH.y);
            }
        }

        // ---- causal mask (diagonal block only) ----
        if (kb == q0) {
            const int r0 = 16 * w + g, r1 = r0 + 8;
#pragma unroll
            for (int nt = 0; nt < 8; nt++) {
                int n0 = 8 * nt + 2 * tig;
                if (n0     > r0) sA[nt][0] = -1e30f;
                if (n0 + 1 > r0) sA[nt][1] = -1e30f;
                if (n0     > r1) sA[nt][2] = -1e30f;
                if (n0 + 1 > r1) sA[nt][3] = -1e30f;
            }
        }

        // ---- online softmax (base-2) ----
        float rx0 = -INFINITY, rx1 = -INFINITY;
#pragma unroll
        for (int nt = 0; nt < 8; nt++) {
            rx0 = fmaxf(rx0, fmaxf(sA[nt][0], sA[nt][1]));
            rx1 = fmaxf(rx1, fmaxf(sA[nt][2], sA[nt][3]));
        }
        rx0 = fmaxf(rx0, __shfl_xor_sync(0xffffffffu, rx0, 1));
        rx0 = fmaxf(rx0, __shfl_xor_sync(0xffffffffu, rx0, 2));
        rx1 = fmaxf(rx1, __shfl_xor_sync(0xffffffffu, rx1, 1));
        rx1 = fmaxf(rx1, __shfl_xor_sync(0xffffffffu, rx1, 2));

        float mn0 = fmaxf(m0r, rx0), mn1 = fmaxf(m1r, rx1);
        float cor0 = fexp2(m0r - mn0), cor1 = fexp2(m1r - mn1);
        m0r = mn0; m1r = mn1;

        float ps0 = 0.0f, ps1 = 0.0f;
#pragma unroll
        for (int nt = 0; nt < 8; nt++) {
            sA[nt][0] = fexp2(sA[nt][0] - mn0);
            sA[nt][1] = fexp2(sA[nt][1] - mn0);
            sA[nt][2] = fexp2(sA[nt][2] - mn1);
            sA[nt][3] = fexp2(sA[nt][3] - mn1);
            ps0 += sA[nt][0] + sA[nt][1];
            ps1 += sA[nt][2] + sA[nt][3];
        }
        ps0 += __shfl_xor_sync(0xffffffffu, ps0, 1);
        ps0 += __shfl_xor_sync(0xffffffffu, ps0, 2);
        ps1 += __shfl_xor_sync(0xffffffffu, ps1, 1);
        ps1 += __shfl_xor_sync(0xffffffffu, ps1, 2);
        l0 = l0 * cor0 + ps0;
        l1 = l1 * cor1 + ps1;
#pragma unroll
        for (int ht = 0; ht < 8; ht++) {
            o[ht][0] *= cor0; o[ht][1] *= cor0;
            o[ht][2] *= cor1; o[ht][3] *= cor1;
        }

        // ---- O += P V (P split hi+lo; 3 MMAs — accuracy-critical) ----
#pragma unroll
        for (int kk = 0; kk < 4; kk++) {
            u32 ph0, pl0, ph1, pl1, ph2, pl2, ph3, pl3;
            split2(sA[2 * kk][0],     sA[2 * kk][1],     ph0, pl0);
            split2(sA[2 * kk][2],     sA[2 * kk][3],     ph1, pl1);
            split2(sA[2 * kk + 1][0], sA[2 * kk + 1][1], ph2, pl2);
            split2(sA[2 * kk + 1][2], sA[2 * kk + 1][3], ph3, pl3);
            const int c0 = 8 * kk + 2 * tig;
#pragma unroll
            for (int ht = 0; ht < 8; ht++) {
                int br = (8 * ht + g) * 40 + c0;
                uint2 VH2 = *(const uint2*)&Vh[br];
                uint2 VL2 = *(const uint2*)&Vl[br];
                mma_bf16(o[ht], ph0, ph1, ph2, ph3, VH2.x, VH2.y);
                mma_bf16(o[ht], ph0, ph1, ph2, ph3, VL2.x, VL2.y);
                mma_bf16(o[ht], pl0, pl1, pl2, pl3, VH2.x, VH2.y);
            }
        }
    }

    // ---- write partials ----
    const int slot = b * NCH_TOT + s;
    const int r0 = 16 * w + g;
    if (tig == 0) {
        part_m[slot * 64 + r0]     = m0r;
        part_m[slot * 64 + r0 + 8] = m1r;
        part_l[slot * 64 + r0]     = l0;
        part_l[slot * 64 + r0 + 8] = l1;
    }
    float* po = part_o + (size_t)slot * 64 * H_;
#pragma unroll
    for (int ht = 0; ht < 8; ht++) {
        int col = 8 * ht + 2 * tig;
        *(float2*)(po + (size_t)r0 * H_ + col)       = make_float2(o[ht][0], o[ht][1]);
        *(float2*)(po + (size_t)(r0 + 8) * H_ + col) = make_float2(o[ht][2], o[ht][3]);
    }
}

// ---------------------------------------------------------------------------
// Combine: 2 threads per row (32 cols each). grid=(16,16), block=256.
// ---------------------------------------------------------------------------
__global__ __launch_bounds__(256) void combine_kernel(float* __restrict__ out)
{
    const int b    = blockIdx.y;
    const int tid  = threadIdx.x;
    const int row  = blockIdx.x * 128 + (tid >> 1);   // 0..2047
    const int half = tid & 1;
    const int qt   = row >> 6;
    const int rr   = row & 63;
    const int nch  = qt / 4 + 1;
    const int base = c_base[qt];

    float mx = -INFINITY;
    for (int ci = 0; ci < nch; ci++)
        mx = fmaxf(mx, part_m[(b * NCH_TOT + base + ci) * 64 + rr]);

    float L = 0.0f;
    float acc[32];
#pragma unroll
    for (int c = 0; c < 32; c++) acc[c] = 0.0f;

    for (int ci = 0; ci < nch; ci++) {
        const int slot = b * NCH_TOT + base + ci;
        float wgt = fexp2(part_m[slot * 64 + rr] - mx);
        L += part_l[slot * 64 + rr] * wgt;
        const float4* po = (const float4*)(part_o + ((size_t)slot * 64 + rr) * H_)
                           + half * 8;
#pragma unroll
        for (int c4 = 0; c4 < 8; c4++) {
            float4 v = po[c4];
            acc[c4 * 4 + 0] += wgt * v.x;
            acc[c4 * 4 + 1] += wgt * v.y;
            acc[c4 * 4 + 2] += wgt * v.z;
            acc[c4 * 4 + 3] += wgt * v.w;
        }
    }

    const float inv = 1.0f / L;
    float4* op = (float4*)(out + ((size_t)b * T_ + row) * H_) + half * 8;
#pragma unroll
    for (int c4 = 0; c4 < 8; c4++)
        op[c4] = make_float4(acc[c4 * 4 + 0] * inv, acc[c4 * 4 + 1] * inv,
                             acc[c4 * 4 + 2] * inv, acc[c4 * 4 + 3] * inv);
}

// ---------------------------------------------------------------------------
extern "C" void kernel_launch(void* const* d_in, const int* in_sizes, int n_in,
                              void* d_out, int out_size)
{
    const float* x  = (const float*)d_in[0];
    const float* wq = (const float*)d_in[1];
    const float* wk = (const float*)d_in[2];
    const float* wv = (const float*)d_in[3];
    float* out = (float*)d_out;

    wconv_kernel<<<384, 256>>>(wq, wk, wv);

    proj_kernel<<<M_ / 64, 128>>>(x);

    dim3 cgrid(NCH_TOT, B_);
    attn_chunk_kernel<<<cgrid, 128>>>();

    dim3 ggrid(T_ / 128, B_);
    combine_kernel<<<ggrid, 256>>>(out);
}

// round 8
// speedup vs baseline: 1.1776x; 1.1776x over previous
#include <cuda_runtime.h>
#include <cuda_bf16.h>
#include <math.h>

#define B_ 16
#define T_ 2048
#define C_ 1024
#define H_ 64
#define M_ (B_ * T_)   // 32768

typedef unsigned int u32;
typedef unsigned short u16;

// ---------------- static device scratch (no allocations) ----------------
__device__ u32 g_qh[(size_t)M_ * 32], g_ql[(size_t)M_ * 32];
__device__ u32 g_kh[(size_t)M_ * 32], g_kl[(size_t)M_ * 32];
__device__ u32 g_vth[(size_t)B_ * 64 * 1024], g_vtl[(size_t)B_ * 64 * 1024];
__device__ u32 g_wth[3 * 64 * 512], g_wtl[3 * 64 * 512];

#define NQT 32
#define NCH_TOT 144
#define NSLOT (B_ * NCH_TOT)        // 2304
__device__ float part_o[(size_t)NSLOT * 64 * H_];
__device__ float part_m[NSLOT * 64];
__device__ float part_l[NSLOT * 64];

__constant__ int c_base[NQT + 1] = {
    0,1,2,3, 4,6,8,10, 12,15,18,21, 24,28,32,36,
    40,45,50,55, 60,66,72,78, 84,91,98,105, 112,120,128,136, 144 };

#define LOG2E 1.4426950408889634f

// ---------------- helpers ----------------
__device__ __host__ __forceinline__ int phys32(int c) {   // c in [0,32)
    return (c & 24) | ((c & 3) << 1) | ((c >> 2) & 1);
}
__device__ __forceinline__ int phys16(int c) {            // c in [0,16)
    return (c & 8) | ((c & 3) << 1) | ((c >> 2) & 1);
}
__device__ __forceinline__ int vt_off(int t) {
    int lp = (t >> 1) & 31;
    return ((t >> 6) << 6) + (phys32(lp) << 1) + (t & 1);
}

__device__ __forceinline__ void split1(float x, u16& h, u16& l) {
    __nv_bfloat16 bh = __float2bfloat16_rn(x);
    float r = x - __bfloat162float(bh);
    __nv_bfloat16 bl = __float2bfloat16_rn(r);
    h = __bfloat16_as_ushort(bh);
    l = __bfloat16_as_ushort(bl);
}
__device__ __forceinline__ void split2(float a, float b, u32& hi, u32& lo) {
    u16 ha, la, hb, lb;
    split1(a, ha, la);
    split1(b, hb, lb);
    hi = (u32)ha | ((u32)hb << 16);
    lo = (u32)la | ((u32)lb << 16);
}
__device__ __forceinline__ float fexp2(float x) {
    float y; asm("ex2.approx.f32 %0,%1;" : "=f"(y) : "f"(x)); return y;
}

__device__ __forceinline__ void mma_bf16(float* c,
    u32 a0, u32 a1, u32 a2, u32 a3, u32 b0, u32 b1) {
    asm volatile(
        "mma.sync.aligned.m16n8k16.row.col.f32.bf16.bf16.f32 "
        "{%0,%1,%2,%3},{%4,%5,%6,%7},{%8,%9},{%0,%1,%2,%3};"
        : "+f"(c[0]), "+f"(c[1]), "+f"(c[2]), "+f"(c[3])
        : "r"(a0), "r"(a1), "r"(a2), "r"(a3), "r"(b0), "r"(b1));
}

// cp.async 16B
#define CP_ASYNC16(dst, src) \
    asm volatile("cp.async.ca.shared.global [%0], [%1], 16;" \
                 :: "r"(dst), "l"(src))
#define CP_COMMIT() asm volatile("cp.async.commit_group;" ::: "memory")
#define CP_WAIT0()  asm volatile("cp.async.wait_group 0;" ::: "memory")

__device__ __forceinline__ u32 smem_u32(const void* p) {
    u32 a;
    asm("{.reg .u64 t; cvta.to.shared.u64 t, %1; cvt.u32.u64 %0, t;}"
        : "=r"(a) : "l"(p));
    return a;
}

// ---------------------------------------------------------------------------
// W pre-convert: W[c][h] f32 -> [w][n][k-pair] bf16 hi/lo, phys16-permuted.
// ---------------------------------------------------------------------------
__global__ void wconv_kernel(const float* __restrict__ wq,
                             const float* __restrict__ wk,
                             const float* __restrict__ wv) {
    int idx = blockIdx.x * 256 + threadIdx.x;
    if (idx >= 3 * 64 * 512) return;
    int w   = idx / (64 * 512);
    int rem = idx % (64 * 512);
    int n   = rem / 512;
    int kp  = rem % 512;
    const float* W = (w == 0) ? wq : (w == 1 ? wk : wv);
    float a = W[(size_t)(2 * kp) * 64 + n];
    float b = W[(size_t)(2 * kp + 1) * 64 + n];
    u32 hi, lo;
    split2(a, b, hi, lo);
    int dst = w * 32768 + n * 512 + (kp & ~15) + phys16(kp & 15);
    g_wth[dst] = hi;
    g_wtl[dst] = lo;
}

// ---------------------------------------------------------------------------
// Projection GEMM, one sel per CTA (low reg pressure).
// grid = (3, 512), block = 128. Permuted epilogues; Q pre-scaled exp2-domain.
// ---------------------------------------------------------------------------
__global__ __launch_bounds__(128) void proj_kernel(const float* __restrict__ x)
{
    __shared__ __align__(16) u32 xh[64 * 20], xl[64 * 20];
    __shared__ __align__(16) u32 wh[64 * 24], wl[64 * 24];

    const int tid  = threadIdx.x;
    const int w    = tid >> 5;
    const int lane = tid & 31;
    const int g    = lane >> 2;
    const int tig  = lane & 3;
    const int sel  = blockIdx.x;
    const int m0   = blockIdx.y * 64;

    const u32* wtH = g_wth + sel * 32768;
    const u32* wtL = g_wtl + sel * 32768;

    float acc[8][4];
#pragma unroll
    for (int nt = 0; nt < 8; nt++)
#pragma unroll
        for (int i = 0; i < 4; i++) acc[nt][i] = 0.0f;

    for (int k0 = 0; k0 < C_; k0 += 32) {
        const int kp0 = k0 >> 1;
        __syncthreads();
#pragma unroll
        for (int q = 0; q < 4; q++) {
            int i  = tid + 128 * q;
            int r  = i >> 3;
            int kq = i & 7;
            float4 v = *(const float4*)(x + (size_t)(m0 + r) * C_ + k0 + kq * 4);
            u32 h0, l0, h1, l1;
            split2(v.x, v.y, h0, l0);
            split2(v.z, v.w, h1, l1);
            int p0 = phys16(2 * kq), p1 = phys16(2 * kq + 1);
            xh[r * 20 + p0] = h0;  xh[r * 20 + p1] = h1;
            xl[r * 20 + p0] = l0;  xl[r * 20 + p1] = l1;
        }
#pragma unroll
        for (int q = 0; q < 4; q++) {
            int i     = tid + 128 * q;
            int plane = i >> 8;          // 0..1
            int rem   = i & 255;
            int n     = rem >> 2;
            int c4    = rem & 3;
            const u32* src = (plane ? wtL : wtH) + n * 512 + kp0 + 4 * c4;
            u32* dst = (plane ? wl : wh) + n * 24 + 4 * c4;
            *(float4*)dst = *(const float4*)src;
        }
        __syncthreads();

        const int rg  = (16 * w + g) * 20;
        const int rg8 = rg + 160;
#pragma unroll
        for (int ks = 0; ks < 2; ks++) {
            const int c0 = 8 * ks + 2 * tig;
            uint2 AH0 = *(const uint2*)&xh[rg  + c0];
            uint2 AH1 = *(const uint2*)&xh[rg8 + c0];
            uint2 AL0 = *(const uint2*)&xl[rg  + c0];
            uint2 AL1 = *(const uint2*)&xl[rg8 + c0];
#pragma unroll
            for (int nt = 0; nt < 8; nt++) {
                int br = (8 * nt + g) * 24 + c0;
                uint2 BH = *(const uint2*)&wh[br];
                uint2 BL = *(const uint2*)&wl[br];
                mma_bf16(acc[nt], AH0.x, AH1.x, AH0.y, AH1.y, BH.x, BH.y);
                mma_bf16(acc[nt], AH0.x, AH1.x, AH0.y, AH1.y, BL.x, BL.y);
                mma_bf16(acc[nt], AL0.x, AL1.x, AL0.y, AL1.y, BH.x, BH.y);
            }
        }
    }

    // ---- epilogue ----
    const int mg = m0 + 16 * w + g;
    if (sel < 2) {
        u32* Hp = sel ? g_kh : g_qh;
        u32* Lp = sel ? g_kl : g_ql;
        const float sc = sel ? 1.0f : (0.125f * LOG2E);
#pragma unroll
        for (int nt = 0; nt < 8; nt++) {
            int pos = phys32(4 * nt + tig);
            u32 hi, lo;
            split2(sc * acc[nt][0], sc * acc[nt][1], hi, lo);
            Hp[(size_t)mg * 32 + pos] = hi;
            Lp[(size_t)mg * 32 + pos] = lo;
            split2(sc * acc[nt][2], sc * acc[nt][3], hi, lo);
            Hp[(size_t)(mg + 8) * 32 + pos] = hi;
            Lp[(size_t)(mg + 8) * 32 + pos] = lo;
        }
    } else {
        u16* VH = (u16*)g_vth;
        u16* VL = (u16*)g_vtl;
        const int b  = mg >> 11;
        const int tt = mg & 2047;
        const int o0 = vt_off(tt);
        const int o8 = vt_off(tt + 8);
#pragma unroll
        for (int nt = 0; nt < 8; nt++) {
            int h0 = 8 * nt + 2 * tig;
            size_t r0 = ((size_t)(b * 64 + h0)) * 2048;
            size_t r1 = ((size_t)(b * 64 + h0 + 1)) * 2048;
            u16 hh, ll;
            split1(acc[nt][0], hh, ll); VH[r0 + o0] = hh; VL[r0 + o0] = ll;
            split1(acc[nt][1], hh, ll); VH[r1 + o0] = hh; VL[r1 + o0] = ll;
            split1(acc[nt][2], hh, ll); VH[r0 + o8] = hh; VL[r0 + o8] = ll;
            split1(acc[nt][3], hh, ll); VH[r1 + o8] = hh; VL[r1 + o8] = ll;
        }
    }
}

// ---------------------------------------------------------------------------
// Split-K attention chunk, cp.async double-buffered staging.
// grid = (144, 16), block = 128. Dynamic smem: 2 stages x 40960 B.
// Stage layout (u32 offsets): Kh 0, Kl 2560, Vh 5120, Vl 7680; stride 40.
// ---------------------------------------------------------------------------
#define STG_U32 10240
#define STG_B   40960

extern __shared__ __align__(16) u32 dsm[];

__global__ __launch_bounds__(128) void attn_chunk_kernel()
{
    const int s = blockIdx.x;
    const int b = blockIdx.y;
    int qt = 0;
    while (c_base[qt + 1] <= s) qt++;
    const int ci = s - c_base[qt];
    const int q0 = qt * 64;

    const int tid  = threadIdx.x;
    const int w    = tid >> 5;
    const int lane = tid & 31;
    const int g    = lane >> 2;
    const int tig  = lane & 3;

    const int kbeg   = ci * 256;
    const int kend   = min(kbeg + 256, q0 + 64);
    const int ntiles = (kend - kbeg) >> 6;

    const u32 sb = smem_u32(dsm);

    // thread-constant staging indices
    const int sr  = tid >> 3;        // 0..15  (row block: r = sr + 16*? no: r=i>>3)
    const int sc4 = tid & 7;

    // prefetch tile 0 -> stage 0
    {
        const float4* KH = (const float4*)(g_kh + ((size_t)b * T_ + kbeg) * 32);
        const float4* KL = (const float4*)(g_kl + ((size_t)b * T_ + kbeg) * 32);
        const float4* VH = (const float4*)(g_vth + (size_t)b * 64 * 1024 + (kbeg >> 1));
        const float4* VL = (const float4*)(g_vtl + (size_t)b * 64 * 1024 + (kbeg >> 1));
#pragma unroll
        for (int q = 0; q < 4; q++) {
            int r = sr + 16 * q;
            u32 off = (u32)(r * 40 + 4 * sc4) * 4;
            CP_ASYNC16(sb + off,         KH + r * 8 + sc4);
            CP_ASYNC16(sb + 10240 + off, KL + r * 8 + sc4);
            CP_ASYNC16(sb + 20480 + off, VH + r * 256 + sc4);
            CP_ASYNC16(sb + 30720 + off, VL + r * 256 + sc4);
        }
        CP_COMMIT();
    }

    // resident Q fragments (overlap with prefetch)
    uint2 qh0[4], qh1[4], ql0[4], ql1[4];
    {
        const size_t qr  = ((size_t)b * T_ + q0 + 16 * w + g) * 32;
        const size_t qr8 = qr + 8 * 32;
#pragma unroll
        for (int ks = 0; ks < 4; ks++) {
            int c0 = 8 * ks + 2 * tig;
            qh0[ks] = *(const uint2*)&g_qh[qr  + c0];
            qh1[ks] = *(const uint2*)&g_qh[qr8 + c0];
            ql0[ks] = *(const uint2*)&g_ql[qr  + c0];
            ql1[ks] = *(const uint2*)&g_ql[qr8 + c0];
        }
    }

    float o[8][4];
#pragma unroll
    for (int ht = 0; ht < 8; ht++)
#pragma unroll
        for (int i = 0; i < 4; i++) o[ht][i] = 0.0f;
    float m0r = -INFINITY, m1r = -INFINITY, l0 = 0.0f, l1 = 0.0f;

    int st = 0;
    for (int t = 0; t < ntiles; t++) {
        const int kb = kbeg + 64 * t;
        CP_WAIT0();
        __syncthreads();

        // prefetch next tile into other stage
        if (t + 1 < ntiles) {
            const int kn = kb + 64;
            const u32 sbn = sb + (st ^ 1) * STG_B;
            const float4* KH = (const float4*)(g_kh + ((size_t)b * T_ + kn) * 32);
            const float4* KL = (const float4*)(g_kl + ((size_t)b * T_ + kn) * 32);
            const float4* VH = (const float4*)(g_vth + (size_t)b * 64 * 1024 + (kn >> 1));
            const float4* VL = (const float4*)(g_vtl + (size_t)b * 64 * 1024 + (kn >> 1));
#pragma unroll
            for (int q = 0; q < 4; q++) {
                int r = sr + 16 * q;
                u32 off = (u32)(r * 40 + 4 * sc4) * 4;
                CP_ASYNC16(sbn + off,         KH + r * 8 + sc4);
                CP_ASYNC16(sbn + 10240 + off, KL + r * 8 + sc4);
                CP_ASYNC16(sbn + 20480 + off, VH + r * 256 + sc4);
                CP_ASYNC16(sbn + 30720 + off, VL + r * 256 + sc4);
            }
            CP_COMMIT();
        }

        const u32* Kh = dsm + st * STG_U32;
        const u32* Kl = Kh + 2560;
        const u32* Vh = Kh + 5120;
        const u32* Vl = Kh + 7680;

        // ---- S = Q K^T ----
        float sA[8][4];
#pragma unroll
        for (int nt = 0; nt < 8; nt++)
#pragma unroll
            for (int i = 0; i < 4; i++) sA[nt][i] = 0.0f;
#pragma unroll
        for (int ks = 0; ks < 4; ks++) {
            const int c0 = 8 * ks + 2 * tig;
#pragma unroll
            for (int nt = 0; nt < 8; nt++) {
                int br = (8 * nt + g) * 40 + c0;
                uint2 BH = *(const uint2*)&Kh[br];
                uint2 BL = *(const uint2*)&Kl[br];
                mma_bf16(sA[nt], qh0[ks].x, qh1[ks].x, qh0[ks].y, qh1[ks].y, BH.x, BH.y);
                mma_bf16(sA[nt], qh0[ks].x, qh1[ks].x, qh0[ks].y, qh1[ks].y, BL.x, BL.y);
                mma_bf16(sA[nt], ql0[ks].x, ql1[ks].x, ql0[ks].y, ql1[ks].y, BH.x, BH.y);
            }
        }

        // ---- causal mask (diagonal block) ----
        if (kb == q0) {
            const int r0 = 16 * w + g, r1 = r0 + 8;
#pragma unroll
            for (int nt = 0; nt < 8; nt++) {
                int n0 = 8 * nt + 2 * tig;
                if (n0     > r0) sA[nt][0] = -1e30f;
                if (n0 + 1 > r0) sA[nt][1] = -1e30f;
                if (n0     > r1) sA[nt][2] = -1e30f;
                if (n0 + 1 > r1) sA[nt][3] = -1e30f;
            }
        }

        // ---- online softmax (base-2) ----
        float rx0 = -INFINITY, rx1 = -INFINITY;
#pragma unroll
        for (int nt = 0; nt < 8; nt++) {
            rx0 = fmaxf(rx0, fmaxf(sA[nt][0], sA[nt][1]));
            rx1 = fmaxf(rx1, fmaxf(sA[nt][2], sA[nt][3]));
        }
        rx0 = fmaxf(rx0, __shfl_xor_sync(0xffffffffu, rx0, 1));
        rx0 = fmaxf(rx0, __shfl_xor_sync(0xffffffffu, rx0, 2));
        rx1 = fmaxf(rx1, __shfl_xor_sync(0xffffffffu, rx1, 1));
        rx1 = fmaxf(rx1, __shfl_xor_sync(0xffffffffu, rx1, 2));

        float mn0 = fmaxf(m0r, rx0), mn1 = fmaxf(m1r, rx1);
        float cor0 = fexp2(m0r - mn0), cor1 = fexp2(m1r - mn1);
        m0r = mn0; m1r = mn1;

        float ps0 = 0.0f, ps1 = 0.0f;
#pragma unroll
        for (int nt = 0; nt < 8; nt++) {
            sA[nt][0] = fexp2(sA[nt][0] - mn0);
            sA[nt][1] = fexp2(sA[nt][1] - mn0);
            sA[nt][2] = fexp2(sA[nt][2] - mn1);
            sA[nt][3] = fexp2(sA[nt][3] - mn1);
            ps0 += sA[nt][0] + sA[nt][1];
            ps1 += sA[nt][2] + sA[nt][3];
        }
        ps0 += __shfl_xor_sync(0xffffffffu, ps0, 1);
        ps0 += __shfl_xor_sync(0xffffffffu, ps0, 2);
        ps1 += __shfl_xor_sync(0xffffffffu, ps1, 1);
        ps1 += __shfl_xor_sync(0xffffffffu, ps1, 2);
        l0 = l0 * cor0 + ps0;
        l1 = l1 * cor1 + ps1;
#pragma unroll
        for (int ht = 0; ht < 8; ht++) {
            o[ht][0] *= cor0; o[ht][1] *= cor0;
            o[ht][2] *= cor1; o[ht][3] *= cor1;
        }

        // ---- O += P V (P split hi+lo; 3 MMAs) ----
#pragma unroll
        for (int kk = 0; kk < 4; kk++) {
            u32 ph0, pl0, ph1, pl1, ph2, pl2, ph3, pl3;
            split2(sA[2 * kk][0],     sA[2 * kk][1],     ph0, pl0);
            split2(sA[2 * kk][2],     sA[2 * kk][3],     ph1, pl1);
            split2(sA[2 * kk + 1][0], sA[2 * kk + 1][1], ph2, pl2);
            split2(sA[2 * kk + 1][2], sA[2 * kk + 1][3], ph3, pl3);
            const int c0 = 8 * kk + 2 * tig;
#pragma unroll
            for (int ht = 0; ht < 8; ht++) {
                int br = (8 * ht + g) * 40 + c0;
                uint2 VH2 = *(const uint2*)&Vh[br];
                uint2 VL2 = *(const uint2*)&Vl[br];
                mma_bf16(o[ht], ph0, ph1, ph2, ph3, VH2.x, VH2.y);
                mma_bf16(o[ht], ph0, ph1, ph2, ph3, VL2.x, VL2.y);
                mma_bf16(o[ht], pl0, pl1, pl2, pl3, VH2.x, VH2.y);
            }
        }
        st ^= 1;
    }

    // ---- write partials ----
    const int slot = b * NCH_TOT + s;
    const int r0 = 16 * w + g;
    if (tig == 0) {
        part_m[slot * 64 + r0]     = m0r;
        part_m[slot * 64 + r0 + 8] = m1r;
        part_l[slot * 64 + r0]     = l0;
        part_l[slot * 64 + r0 + 8] = l1;
    }
    float* po = part_o + (size_t)slot * 64 * H_;
#pragma unroll
    for (int ht = 0; ht < 8; ht++) {
        int col = 8 * ht + 2 * tig;
        *(float2*)(po + (size_t)r0 * H_ + col)       = make_float2(o[ht][0], o[ht][1]);
        *(float2*)(po + (size_t)(r0 + 8) * H_ + col) = make_float2(o[ht][2], o[ht][3]);
    }
}

// ---------------------------------------------------------------------------
// Combine: 4 threads per row (16 cols each). grid=(16,16), block=512.
// ---------------------------------------------------------------------------
__global__ __launch_bounds__(512) void combine_kernel(float* __restrict__ out)
{
    const int b    = blockIdx.y;
    const int tid  = threadIdx.x;
    const int row  = blockIdx.x * 128 + (tid >> 2);   // 0..2047
    const int quad = tid & 3;
    const int qt   = row >> 6;
    const int rr   = row & 63;
    const int nch  = qt / 4 + 1;
    const int base = c_base[qt];

    float mx = -INFINITY;
    for (int ci = 0; ci < nch; ci++)
        mx = fmaxf(mx, part_m[(b * NCH_TOT + base + ci) * 64 + rr]);

    float L = 0.0f;
    float acc[16];
#pragma unroll
    for (int c = 0; c < 16; c++) acc[c] = 0.0f;

    for (int ci = 0; ci < nch; ci++) {
        const int slot = b * NCH_TOT + base + ci;
        float wgt = fexp2(part_m[slot * 64 + rr] - mx);
        L += part_l[slot * 64 + rr] * wgt;
        const float4* po = (const float4*)(part_o + ((size_t)slot * 64 + rr) * H_)
                           + quad * 4;
#pragma unroll
        for (int c4 = 0; c4 < 4; c4++) {
            float4 v = po[c4];
            acc[c4 * 4 + 0] += wgt * v.x;
            acc[c4 * 4 + 1] += wgt * v.y;
            acc[c4 * 4 + 2] += wgt * v.z;
            acc[c4 * 4 + 3] += wgt * v.w;
        }
    }

    const float inv = 1.0f / L;
    float4* op = (float4*)(out + ((size_t)b * T_ + row) * H_) + quad * 4;
#pragma unroll
    for (int c4 = 0; c4 < 4; c4++)
        op[c4] = make_float4(acc[c4 * 4 + 0] * inv, acc[c4 * 4 + 1] * inv,
                             acc[c4 * 4 + 2] * inv, acc[c4 * 4 + 3] * inv);
}

// ---------------------------------------------------------------------------
extern "C" void kernel_launch(void* const* d_in, const int* in_sizes, int n_in,
                              void* d_out, int out_size)
{
    const float* x  = (const float*)d_in[0];
    const float* wq = (const float*)d_in[1];
    const float* wk = (const float*)d_in[2];
    const float* wv = (const float*)d_in[3];
    float* out = (float*)d_out;

    cudaFuncSetAttribute(attn_chunk_kernel,
                         cudaFuncAttributeMaxDynamicSharedMemorySize, 2 * STG_B);

    wconv_kernel<<<384, 256>>>(wq, wk, wv);

    dim3 pgrid(3, M_ / 64);
    proj_kernel<<<pgrid, 128>>>(x);

    dim3 cgrid(NCH_TOT, B_);
    attn_chunk_kernel<<<cgrid, 128, 2 * STG_B>>>();

    dim3 ggrid(T_ / 128, B_);
    combine_kernel<<<ggrid, 512>>>(out);
}